// round 16
// baseline (speedup 1.0000x reference)
#include <cuda_runtime.h>
#include <cuda_bf16.h>
#include <cuda_fp16.h>
#include <cstdint>
#include <math.h>

#define Bdim 128
#define Tdim 32
#define Edim 512
#define Hdim 512
#define Vdim 10000
#define LFdim 49
#define G4 2048
#define MT 4096
#define Kdim 512

// ---------------- scratch (__device__ globals; no allocs allowed) ----------
__device__ float g_mf[Bdim*Edim];              // fp32 mean-pooled features
__device__ float g_c[Bdim*Hdim];
__device__ float g_gx[(size_t)MT*G4];          // compact rows (bias folded)
__device__ float g_pbias[G4];                  // permuted b_ih+b_hh

__device__ int g_nact[Tdim];
__device__ int g_off[Tdim+1];
__device__ int g_Mc;
__device__ int g_map[MT];   // row -> (t<<8)|b ; bit16 set = masked (zero output)
__device__ unsigned int g_sync2[128];          // per-mtile counters at [mtile*32]

__device__ __half g_h016[Bdim*Hdim];           // initial hidden state (fp16)
__device__ __half g_emb16[(size_t)MT*Edim];    // gathered embeddings (fp16)
__device__ __half g_wih16h[(size_t)G4*Edim], g_wih16l[(size_t)G4*Edim]; // perm, x64
__device__ __half g_whh16h[(size_t)G4*Hdim], g_whh16l[(size_t)G4*Hdim]; // perm, x64
__device__ __half g_fwh16[(size_t)Vdim*Hdim];  // 64x prescaled fp16
__device__ __half g_hall16[(size_t)MT*Hdim];   // compact hidden states, fp16

// ---------------- PTX helpers (sm_80-era: legal on base sm_100) ------------
__device__ __forceinline__ uint32_t smem_to_u32(const void* p) {
    uint32_t a;
    asm("{ .reg .u64 t; cvta.to.shared.u64 t, %1; cvt.u32.u64 %0, t; }" : "=r"(a) : "l"(p));
    return a;
}
__device__ __forceinline__ void cp16(uint32_t dst, const void* src, bool pred) {
    int sz = pred ? 16 : 0;
    asm volatile("cp.async.cg.shared.global [%0], [%1], 16, %2;"
                 :: "r"(dst), "l"(src), "r"(sz) : "memory");
}
#define CP_COMMIT() asm volatile("cp.async.commit_group;" ::: "memory")
#define CP_WAIT1()  asm volatile("cp.async.wait_group 1;" ::: "memory")
#define CP_WAIT0()  asm volatile("cp.async.wait_group 0;" ::: "memory")
#define LDSM4(r, addr) \
    asm volatile("ldmatrix.sync.aligned.m8n8.x4.shared.b16 {%0,%1,%2,%3}, [%4];" \
        : "=r"((r)[0]), "=r"((r)[1]), "=r"((r)[2]), "=r"((r)[3]) : "r"(addr))

__device__ __forceinline__ void mma16816h(float* c, const uint32_t* a, const uint32_t* b) {
    asm volatile("mma.sync.aligned.m16n8k16.row.col.f32.f16.f16.f32 "
        "{%0,%1,%2,%3}, {%4,%5,%6,%7}, {%8,%9}, {%0,%1,%2,%3};"
        : "+f"(c[0]), "+f"(c[1]), "+f"(c[2]), "+f"(c[3])
        : "r"(a[0]), "r"(a[1]), "r"(a[2]), "r"(a[3]), "r"(b[0]), "r"(b[1]));
}

// XOR swizzle for 64B-row tiles: row r, 16B chunk q
__device__ __forceinline__ uint32_t sw_off(int r, int q) {
    return (uint32_t)(r*64 + ((q ^ ((r >> 1) & 3)) << 4));
}

__device__ __forceinline__ float sigf(float x) { return 1.0f / (1.0f + expf(-x)); }

__device__ __forceinline__ uint32_t pack_h2(float a, float b) {
    __half2 v = __floats2half2_rn(a, b);
    return *(uint32_t*)&v;
}

#define INV64 0.015625f

// ---------------------------------------------------------------------------
// setup: n_active(t), offsets, full row map (active + masked pads), biases
__global__ void setup_kernel(const int* __restrict__ lengths,
                             const float* __restrict__ b_ih,
                             const float* __restrict__ b_hh) {
    __shared__ int s_len[Bdim];
    __shared__ int s_moff[Bdim];     // prefix of masked counts per batch
    int tid = threadIdx.x;
    if (tid < 128) g_sync2[tid] = 0u;
    if (tid < Bdim) s_len[tid] = lengths[tid];
    __syncthreads();
    if (tid < Tdim) {
        int cnt = 0;
        for (int b = 0; b < Bdim; b++) cnt += (s_len[b] > tid) ? 1 : 0;
        g_nact[tid] = cnt;
    }
    __syncthreads();
    if (tid == 0) {
        int acc = 0;
        for (int t = 0; t < Tdim; t++) { g_off[t] = acc; acc += g_nact[t]; }
        g_off[Tdim] = acc;
        g_Mc = acc;
        int macc = 0;
        for (int b = 0; b < Bdim; b++) { s_moff[b] = macc; macc += Tdim - s_len[b]; }
    }
    __syncthreads();
    int Mc = g_Mc;
    for (int r = tid; r < Mc; r += 256) {
        int t = 0;
        while (t < Tdim - 1 && r >= g_off[t+1]) t++;
        g_map[r] = (t << 8) | (r - g_off[t]);
    }
    for (int i = tid; i < MT; i += 256) {
        int b = i >> 5, t = i & 31;
        if (t >= s_len[b]) {
            int rp = Mc + s_moff[b] + (t - s_len[b]);
            g_map[rp] = (t << 8) | b | 0x10000;
        }
    }
    for (int i = tid; i < G4; i += 256) {
        int j = i >> 2, g = i & 3;
        g_pbias[i] = b_ih[g*512 + j] + b_hh[g*512 + j];
    }
}

// ---------------------------------------------------------------------------
// mean pool -> fp32
__global__ void meanpool_kernel(const float* __restrict__ features) {
    int b = blockIdx.x, k = threadIdx.x;
    const float* p = features + (size_t)b*LFdim*512 + k;
    float s = 0.f;
    #pragma unroll
    for (int l = 0; l < LFdim; l++) s += p[l*512];
    g_mf[b*512 + k] = s * (1.0f/LFdim);
}

// exact fp32 init GEMM: h0 (-> fp16) and c0 (fp32).
__global__ void __launch_bounds__(256)
init_kernel(const float* __restrict__ ihw, const float* __restrict__ icw,
            const float* __restrict__ ihb, const float* __restrict__ icb) {
    __shared__ float ws[8*512];      // 16 KB: this block's 8 weight rows
    const int nb = blockIdx.x * 8;   // stacked unit base (0..1016)
    const int tid = threadIdx.x;
    for (int i = tid; i < 8*128; i += 256) {
        int rr = i >> 7, c4 = (i & 127) * 4;
        int n = nb + rr;
        const float* src = (n < 512) ? (ihw + (size_t)n*512 + c4)
                                     : (icw + (size_t)(n-512)*512 + c4);
        *(float4*)(ws + rr*512 + c4) = *(const float4*)src;
    }
    __syncthreads();

    const int u = tid & 7;
    const int bg = tid >> 3;
    const int n = nb + u;
    const float bias = (n < 512) ? ihb[n] : icb[n - 512];
    const float* w = ws + u*512;
    const float* m0 = g_mf + (bg*4 + 0)*512;
    const float* m1 = g_mf + (bg*4 + 1)*512;
    const float* m2 = g_mf + (bg*4 + 2)*512;
    const float* m3 = g_mf + (bg*4 + 3)*512;
    float a0 = 0.f, a1 = 0.f, a2 = 0.f, a3 = 0.f;
    #pragma unroll 8
    for (int k = 0; k < 512; k += 4) {
        float4 wv = *(const float4*)(w + k);
        float4 x0 = *(const float4*)(m0 + k);
        float4 x1 = *(const float4*)(m1 + k);
        float4 x2 = *(const float4*)(m2 + k);
        float4 x3 = *(const float4*)(m3 + k);
        a0 = fmaf(wv.x, x0.x, fmaf(wv.y, x0.y, fmaf(wv.z, x0.z, fmaf(wv.w, x0.w, a0))));
        a1 = fmaf(wv.x, x1.x, fmaf(wv.y, x1.y, fmaf(wv.z, x1.z, fmaf(wv.w, x1.w, a1))));
        a2 = fmaf(wv.x, x2.x, fmaf(wv.y, x2.y, fmaf(wv.z, x2.z, fmaf(wv.w, x2.w, a2))));
        a3 = fmaf(wv.x, x3.x, fmaf(wv.y, x3.y, fmaf(wv.z, x3.z, fmaf(wv.w, x3.w, a3))));
    }
    float acc[4] = {a0 + bias, a1 + bias, a2 + bias, a3 + bias};
    #pragma unroll
    for (int i = 0; i < 4; i++) {
        int b = bg*4 + i;
        if (n < 512) g_h016[b*512 + n] = __float2half_rn(acc[i]);
        else         g_c[b*512 + n - 512] = acc[i];
    }
}

// ---------------------------------------------------------------------------
// gather embeddings into compact rows as fp16 (zero pads emb & hall16)
__global__ void gather16_kernel(const float* __restrict__ emb,
                                const int* __restrict__ cap) {
    int r = blockIdx.x;
    int v = g_map[r];
    int c4 = threadIdx.x * 4;          // 128 threads x 4 = 512
    if (v & 0x10000) {
        uint2 z = make_uint2(0u, 0u);
        *(uint2*)(g_emb16 + (size_t)r*Edim + c4) = z;
        *(uint2*)(g_hall16 + (size_t)r*Hdim + c4) = z;
        return;
    }
    int t = (v >> 8) & 0xFF, b = v & 0xFF;
    int tok = cap[b*Tdim + t];
    float4 x = *(const float4*)(emb + (size_t)tok*Edim + c4);
    *(uint2*)(g_emb16 + (size_t)r*Edim + c4) =
        make_uint2(pack_h2(x.x, x.y), pack_h2(x.z, x.w));
}

// split BOTH recurrent weights: gate-permuted, fp16 2-term, x64 prescale
__global__ void split_permute2_kernel(const float* __restrict__ Wih,
                                      const float* __restrict__ Whh) {
    int bi = blockIdx.x;
    const float* W = (bi < 1024) ? Wih : Whh;
    __half* hi = (bi < 1024) ? g_wih16h : g_whh16h;
    __half* lo = (bi < 1024) ? g_wih16l : g_whh16l;
    int idx = (bi & 1023)*256 + threadIdx.x;
    int r = idx >> 7, c4 = (idx & 127) * 4;
    int j = r >> 2, g = r & 3;
    float4 x = *(const float4*)(W + (size_t)(g*512 + j)*512 + c4);
    x.x *= 64.f; x.y *= 64.f; x.z *= 64.f; x.w *= 64.f;
    float hx = __half2float(__float2half_rn(x.x));
    float hy = __half2float(__float2half_rn(x.y));
    float hz = __half2float(__float2half_rn(x.z));
    float hw = __half2float(__float2half_rn(x.w));
    *(uint2*)(hi + (size_t)r*512 + c4) = make_uint2(pack_h2(x.x, x.y), pack_h2(x.z, x.w));
    *(uint2*)(lo + (size_t)r*512 + c4) =
        make_uint2(pack_h2(x.x - hx, x.y - hy), pack_h2(x.z - hz, x.w - hw));
}

// vectorized fp16 convert with 64x prescale (fc_w, single-term)
__global__ void conv4_f16s(const float* __restrict__ s,
                           __half* __restrict__ hi, int n4) {
    int i = blockIdx.x*256 + threadIdx.x;
    if (i >= n4) return;
    float4 x = ((const float4*)s)[i];
    ((uint2*)hi)[i] = make_uint2(pack_h2(x.x*64.f, x.y*64.f), pack_h2(x.z*64.f, x.w*64.f));
}

// ---------------------------------------------------------------------------
// gx GEMM: fp16 A-single + W-double (x64). C = (A@(Wh+Wl)^T)/64 + pbias.
// BK=64, 3-stage single-sync pipeline: 8 iterations, 1 barrier each.
#define GXS_A  0
#define GXS_BH 16384
#define GXS_BL 32768
#define GX_STAGE 49152
#define GX_DSM (3*GX_STAGE)     // 144 KB

__global__ void __launch_bounds__(256)
gx_gemm(const __half* __restrict__ A, const __half* __restrict__ Bh,
        const __half* __restrict__ Bl, float* __restrict__ C,
        const float* __restrict__ b1)
{
    const int m0 = blockIdx.y * 128;
    if (m0 >= g_Mc) return;
    extern __shared__ char smem[];
    const uint32_t sbase = smem_to_u32(smem);
    const int tid = threadIdx.x;
    const int lane = tid & 31, wid = tid >> 5;
    const int wm = wid >> 2, wn = wid & 3;
    const int n0 = blockIdx.x * 128;
    const int N = G4;

    float c[4][4][4];
    #pragma unroll
    for (int i = 0; i < 4; i++)
        #pragma unroll
        for (int j = 0; j < 4; j++)
            { c[i][j][0]=0.f; c[i][j][1]=0.f; c[i][j][2]=0.f; c[i][j][3]=0.f; }

    // one stage = kc pair (2kb, 2kb+1): A 2x8KB, Bh 2x8KB, Bl 2x8KB
    auto load_stage = [&](int kb, int stage) {
        const uint32_t st = sbase + stage * GX_STAGE;
        #pragma unroll
        for (int i = 0; i < 4; i++) {
            int g = tid + 256*i;               // 0..1023
            int sub = g >> 9, rem = g & 511;
            int r = rem >> 2, q = rem & 3;
            int k0 = (2*kb + sub) * 32;
            uint32_t off = (uint32_t)(sub*8192) + sw_off(r, q);
            cp16(st + GXS_A + off,  A  + (size_t)(m0 + r)*Kdim + k0 + q*8, true);
            size_t bo = (size_t)(n0 + r)*Kdim + k0 + q*8;
            cp16(st + GXS_BH + off, Bh + bo, true);
            cp16(st + GXS_BL + off, Bl + bo, true);
        }
        CP_COMMIT();
    };

    load_stage(0, 0);
    load_stage(1, 1);
    for (int kb = 0; kb < 8; kb++) {
        int stage = kb % 3;
        if (kb + 1 < 8) CP_WAIT1(); else CP_WAIT0();
        __syncthreads();
        if (kb + 2 < 8) load_stage(kb + 2, (kb + 2) % 3);
        const uint32_t st = sbase + stage * GX_STAGE;

        #pragma unroll
        for (int sub = 0; sub < 2; sub++) {
            const uint32_t saA = st + GXS_A  + sub*8192;
            const uint32_t saH = st + GXS_BH + sub*8192;
            const uint32_t saL = st + GXS_BL + sub*8192;
            #pragma unroll
            for (int kh = 0; kh < 2; kh++) {
                uint32_t aH[4][4];
                #pragma unroll
                for (int mf = 0; mf < 4; mf++) {
                    int row  = wm*64 + mf*16 + (lane & 7) + ((lane >> 3) & 1)*8;
                    int kcol = kh*16 + ((lane >> 4) & 1)*8;
                    LDSM4(aH[mf], saA + sw_off(row, kcol >> 3));
                }
                uint32_t bHf[4][2], bLf[4][2];
                #pragma unroll
                for (int np = 0; np < 2; np++) {
                    int row  = wn*32 + np*16 + (lane & 7) + ((lane >> 4) & 1)*8;
                    int kcol = ((lane >> 3) & 1)*8 + kh*16;
                    uint32_t off = sw_off(row, kcol >> 3);
                    uint32_t r4[4];
                    LDSM4(r4, saH + off);
                    bHf[np*2][0]=r4[0]; bHf[np*2][1]=r4[1];
                    bHf[np*2+1][0]=r4[2]; bHf[np*2+1][1]=r4[3];
                    LDSM4(r4, saL + off);
                    bLf[np*2][0]=r4[0]; bLf[np*2][1]=r4[1];
                    bLf[np*2+1][0]=r4[2]; bLf[np*2+1][1]=r4[3];
                }
                #pragma unroll
                for (int mf = 0; mf < 4; mf++)
                    #pragma unroll
                    for (int nf = 0; nf < 4; nf++) {
                        mma16816h(c[mf][nf], aH[mf], bHf[nf]);
                        mma16816h(c[mf][nf], aH[mf], bLf[nf]);
                    }
            }
        }
    }

    #pragma unroll
    for (int mf = 0; mf < 4; mf++) {
        #pragma unroll
        for (int nf = 0; nf < 4; nf++) {
            int m = m0 + wm*64 + mf*16 + (lane >> 2);
            int n = n0 + wn*32 + nf*8 + 2*(lane & 3);
            #pragma unroll
            for (int half = 0; half < 2; half++) {
                int mm = m + half*8;
                float v0 = c[mf][nf][half*2]*INV64   + b1[n];
                float v1 = c[mf][nf][half*2+1]*INV64 + b1[n+1];
                *(float2*)(C + (size_t)mm*N + n) = make_float2(v0, v1);
            }
        }
    }
}

// ---------------------------------------------------------------------------
// fc GEMM: fp16 single-term. A resident (128 KB), B 3-stage BK=64, 8 barriers.
#define FC_A    0               // 16 chunks x 8 KB = 128 KB
#define FC_BST  131072          // 3 stages x 16 KB (2 chunks x 8 KB each)
#define FC_DSM  (131072 + 3*16384)   // 180224 B

__global__ void __launch_bounds__(256)
fc_gemm(const __half* __restrict__ A, const __half* __restrict__ Bh,
        float* __restrict__ C, const float* __restrict__ b1)
{
    const int m0 = blockIdx.y * 128;
    extern __shared__ char smem[];
    const uint32_t sbase = smem_to_u32(smem);
    const int tid = threadIdx.x;
    const int lane = tid & 31, wid = tid >> 5;
    const int wm = wid >> 2, wn = wid & 3;
    const int n0 = blockIdx.x * 128;
    const int N = Vdim;

    float c[4][4][4];
    #pragma unroll
    for (int i = 0; i < 4; i++)
        #pragma unroll
        for (int j = 0; j < 4; j++)
            { c[i][j][0]=0.f; c[i][j][1]=0.f; c[i][j][2]=0.f; c[i][j][3]=0.f; }

    if (m0 < g_Mc) {
        // B stage = kc pair: 2 chunks x 8 KB
        auto loadB = [&](int kb, int stage) {
            const uint32_t st = sbase + FC_BST + stage*16384;
            #pragma unroll
            for (int i = 0; i < 4; i++) {
                int g = tid + 256*i;           // 0..1023
                int sub = g >> 9, rem = g & 511;
                int r = rem >> 2, q = rem & 3;
                int k0 = (2*kb + sub) * 32;
                int nr = n0 + r;
                bool bp = nr < N;
                size_t bo = (size_t)(bp ? nr : (N-1))*Kdim + k0 + q*8;
                cp16(st + (uint32_t)(sub*8192) + sw_off(r, q), Bh + bo, bp);
            }
            CP_COMMIT();
        };

        // full A tile: 128 rows x 512 k = 8192 x 16B groups (32/thread)
        {
            #pragma unroll
            for (int i = 0; i < 32; i++) {
                int g = tid + 256*i;
                int kc = g >> 9, rem = g & 511;
                int r = rem >> 2, q = rem & 3;
                cp16(sbase + FC_A + (uint32_t)(kc*8192) + sw_off(r, q),
                     A + (size_t)(m0 + r)*Kdim + kc*32 + q*8, true);
            }
            loadB(0, 0);
            CP_COMMIT();       // group 0 = A + B stage 0
        }
        loadB(1, 1);           // group 1

        for (int kb = 0; kb < 8; kb++) {
            int stage = kb % 3;
            if (kb + 1 < 8) CP_WAIT1(); else CP_WAIT0();
            __syncthreads();
            if (kb + 2 < 8) loadB(kb + 2, (kb + 2) % 3);
            const uint32_t st = sbase + FC_BST + stage*16384;

            #pragma unroll
            for (int sub = 0; sub < 2; sub++) {
                int kc = 2*kb + sub;
                const uint32_t saA = sbase + FC_A + (uint32_t)(kc*8192);
                const uint32_t saB = st + sub*8192;
                #pragma unroll
                for (int kh = 0; kh < 2; kh++) {
                    uint32_t aH[4][4];
                    #pragma unroll
                    for (int mf = 0; mf < 4; mf++) {
                        int row  = wm*64 + mf*16 + (lane & 7) + ((lane >> 3) & 1)*8;
                        int kcol = kh*16 + ((lane >> 4) & 1)*8;
                        LDSM4(aH[mf], saA + sw_off(row, kcol >> 3));
                    }
                    uint32_t bHf[4][2];
                    #pragma unroll
                    for (int np = 0; np < 2; np++) {
                        int row  = wn*32 + np*16 + (lane & 7) + ((lane >> 4) & 1)*8;
                        int kcol = ((lane >> 3) & 1)*8 + kh*16;
                        uint32_t r4[4];
                        LDSM4(r4, saB + sw_off(row, kcol >> 3));
                        bHf[np*2][0]=r4[0]; bHf[np*2][1]=r4[1];
                        bHf[np*2+1][0]=r4[2]; bHf[np*2+1][1]=r4[3];
                    }
                    #pragma unroll
                    for (int mf = 0; mf < 4; mf++)
                        #pragma unroll
                        for (int nf = 0; nf < 4; nf++)
                            mma16816h(c[mf][nf], aH[mf], bHf[nf]);
                }
            }
        }
    }

    #pragma unroll
    for (int mf = 0; mf < 4; mf++) {
        #pragma unroll
        for (int nf = 0; nf < 4; nf++) {
            int m = m0 + wm*64 + mf*16 + (lane >> 2);
            int n = n0 + wn*32 + nf*8 + 2*(lane & 3);
            if (n >= N) continue;
            #pragma unroll
            for (int half = 0; half < 2; half++) {
                int mm = m + half*8;
                int v = g_map[mm];
                int t = (v >> 8) & 0xFF, b = v & 0xFF;
                float2 o;
                if (v & 0x10000) {
                    o = make_float2(0.f, 0.f);
                } else {
                    o = make_float2(c[mf][nf][half*2]*INV64   + b1[n],
                                    c[mf][nf][half*2+1]*INV64 + b1[n+1]);
                }
                *(float2*)(C + ((size_t)(b*Tdim + t))*Vdim + n) = o;
            }
        }
    }
}

// ---------------------------------------------------------------------------
// Persistent recurrence, fp16. W resident; FULL A tile (32x512, 32KB) loaded
// once per step -> ZERO barriers inside the 16-kc MMA loop.
#define PK_WH    0
#define PK_WL    65536
#define PK_A     131072          // 16 chunks x 2 KB = 32 KB
#define PK_GATES 163840          // float[32*66] = 8448 B
#define PK_CST   172288          // float[512]   = 2048 B
#define PK_BYTES 174336

__global__ void __launch_bounds__(256)
persist_step_kernel() {
    extern __shared__ char sm[];
    const uint32_t sbase = smem_to_u32(sm);
    const int tid = threadIdx.x;
    const int lane = tid & 31, wid = tid >> 5;
    const int wm = wid >> 2, wn = wid & 3;   // 2m x 4n warp grid (32 x 64 tile)
    const int nslice = blockIdx.x & 31;
    const int mtile = blockIdx.x >> 5;       // 0..3
    const int n0 = nslice * 64;
    const int m0 = mtile * 32;
    unsigned int* syncc = &g_sync2[mtile * 32];

    // preload W slice: 16 chunks of [64 rows x 32 k], hi+lo (resident)
    {
        int r = tid >> 2, q = tid & 3;
        #pragma unroll
        for (int kc = 0; kc < 16; kc++) {
            uint32_t off = (uint32_t)(kc*4096) + sw_off(r, q);
            size_t go = (size_t)(n0 + r)*Hdim + kc*32 + q*8;
            cp16(sbase + PK_WH + off, g_whh16h + go, true);
            cp16(sbase + PK_WL + off, g_whh16l + go, true);
        }
        CP_COMMIT();
    }
    float* cst = (float*)(sm + PK_CST);      // [32 rows x 16 units]
    for (int i = tid; i < 512; i += 256) {
        int r = i >> 4, u = i & 15;
        cst[i] = g_c[(m0 + r)*Hdim + (n0 >> 2) + u];
    }
    CP_WAIT0();
    __syncthreads();

    float* gs = (float*)(sm + PK_GATES);
    int scount = 0;

    for (int t = 0; t < Tdim; t++) {
        const int nact = g_nact[t];
        if (mtile > 0 && nact <= m0) break;  // nact non-increasing: done forever
        const __half* Ah = (t == 0) ? g_h016 : (g_hall16 + (size_t)g_off[t-1]*Hdim);

        {
            // load FULL A tile: 32 rows x 512 k = 2048 x 16B groups, 8/thread
            for (int i = tid; i < 2048; i += 256) {
                int kc = i >> 7, rem = i & 127;
                int r = rem >> 2, q = rem & 3;
                cp16(sbase + PK_A + (uint32_t)(kc*2048) + sw_off(r, q),
                     Ah + (size_t)(m0 + r)*Hdim + kc*32 + q*8, true);
            }
            CP_COMMIT();
            CP_WAIT0();
            __syncthreads();

            float acc[2][4];
            #pragma unroll
            for (int j = 0; j < 2; j++)
                { acc[j][0]=0.f; acc[j][1]=0.f; acc[j][2]=0.f; acc[j][3]=0.f; }

            // barrier-free MMA loop: W resident, A static
            #pragma unroll 4
            for (int kc = 0; kc < 16; kc++) {
                const uint32_t sa  = sbase + PK_A  + (uint32_t)(kc*2048);
                const uint32_t wbH = sbase + PK_WH + (uint32_t)(kc*4096);
                const uint32_t wbL = sbase + PK_WL + (uint32_t)(kc*4096);
                #pragma unroll
                for (int kh = 0; kh < 2; kh++) {
                    uint32_t aH[4];
                    {
                        int row  = wm*16 + (lane & 7) + ((lane >> 3) & 1)*8;
                        int kcol = kh*16 + ((lane >> 4) & 1)*8;
                        LDSM4(aH, sa + sw_off(row, kcol >> 3));
                    }
                    uint32_t bH[2][2], bL[2][2];
                    {
                        int row  = wn*16 + (lane & 7) + ((lane >> 4) & 1)*8;
                        int kcol = ((lane >> 3) & 1)*8 + kh*16;
                        uint32_t off = sw_off(row, kcol >> 3);
                        uint32_t r4[4];
                        LDSM4(r4, wbH + off);
                        bH[0][0]=r4[0]; bH[0][1]=r4[1]; bH[1][0]=r4[2]; bH[1][1]=r4[3];
                        LDSM4(r4, wbL + off);
                        bL[0][0]=r4[0]; bL[0][1]=r4[1]; bL[1][0]=r4[2]; bL[1][1]=r4[3];
                    }
                    #pragma unroll
                    for (int nf = 0; nf < 2; nf++) {
                        mma16816h(acc[nf], aH, bH[nf]);
                        mma16816h(acc[nf], aH, bL[nf]);
                    }
                }
            }

            // gates*(1/64) + gx -> smem (stride 66)
            const int goff = g_off[t];
            #pragma unroll
            for (int nf = 0; nf < 2; nf++) {
                int rl = wm*16 + (lane >> 2);
                int nl = wn*16 + nf*8 + 2*(lane & 3);
                #pragma unroll
                for (int half = 0; half < 2; half++) {
                    int rr = rl + half*8;
                    float2 gx2 = *(const float2*)(g_gx + (size_t)(goff + m0 + rr)*G4 + n0 + nl);
                    gs[rr*66 + nl]     = acc[nf][half*2]*INV64   + gx2.x;
                    gs[rr*66 + nl + 1] = acc[nf][half*2+1]*INV64 + gx2.y;
                }
            }
            __syncthreads();

            // cell update: 32 rows x 16 units = 512 items, 2/thread
            #pragma unroll
            for (int p = 0; p < 2; p++) {
                int idx = tid + 256*p;
                int row = idx >> 4, u = idx & 15;
                int rg = m0 + row;
                if (rg < nact) {
                    float gi = gs[row*66 + u*4 + 0];
                    float gf = gs[row*66 + u*4 + 1];
                    float gc = gs[row*66 + u*4 + 2];
                    float go = gs[row*66 + u*4 + 3];
                    float cc = cst[row*16 + u];
                    cc = sigf(gf)*cc + sigf(gi)*tanhf(gc);
                    float hv = sigf(go)*tanhf(cc);
                    cst[row*16 + u] = cc;
                    int jg = (n0 >> 2) + u;
                    g_hall16[(size_t)(goff + rg)*Hdim + jg] = __float2half_rn(hv);
                }
            }
        }

        // per-mtile grid sync (32 blocks); also fences PK_A reuse next step
        scount++;
        __syncthreads();
        if (tid == 0) {
            __threadfence();
            atomicAdd(syncc, 1u);
            unsigned target = 32u * (unsigned)scount;
            while (atomicAdd(syncc, 0u) < target) { __nanosleep(32); }
            __threadfence();
        }
        __syncthreads();
    }
}

// ---------------------------------------------------------------------------
extern "C" void kernel_launch(void* const* d_in, const int* in_sizes, int n_in,
                              void* d_out, int out_size) {
    const float* features  = (const float*)d_in[0];
    const int*   captions  = (const int*)  d_in[1];
    const int*   lengths   = (const int*)  d_in[2];
    const float* embedding = (const float*)d_in[3];
    const float* W_ih      = (const float*)d_in[4];
    const float* W_hh      = (const float*)d_in[5];
    const float* b_ih      = (const float*)d_in[6];
    const float* b_hh      = (const float*)d_in[7];
    const float* fc_w      = (const float*)d_in[8];
    const float* fc_b      = (const float*)d_in[9];
    const float* ihw       = (const float*)d_in[10];
    const float* ihb       = (const float*)d_in[11];
    const float* icw       = (const float*)d_in[12];
    const float* icb       = (const float*)d_in[13];
    float* out = (float*)d_out;

    float *gx, *pbias;
    __half *emb16, *wih16h, *wih16l, *fwh16, *hall16;
    cudaGetSymbolAddress((void**)&gx, g_gx);
    cudaGetSymbolAddress((void**)&pbias, g_pbias);
    cudaGetSymbolAddress((void**)&emb16, g_emb16);
    cudaGetSymbolAddress((void**)&wih16h, g_wih16h);
    cudaGetSymbolAddress((void**)&wih16l, g_wih16l);
    cudaGetSymbolAddress((void**)&fwh16, g_fwh16);
    cudaGetSymbolAddress((void**)&hall16, g_hall16);

    cudaFuncSetAttribute(gx_gemm, cudaFuncAttributeMaxDynamicSharedMemorySize, GX_DSM);
    cudaFuncSetAttribute(fc_gemm, cudaFuncAttributeMaxDynamicSharedMemorySize, FC_DSM);
    cudaFuncSetAttribute(persist_step_kernel, cudaFuncAttributeMaxDynamicSharedMemorySize, PK_BYTES);

    // 0. row map + biases + sync reset
    setup_kernel<<<1, 256>>>(lengths, b_ih, b_hh);

    // 1. mean pool + exact fp32 init (h0 -> fp16, c0 fp32)
    meanpool_kernel<<<Bdim, 512>>>(features);
    init_kernel<<<128, 256>>>(ihw, icw, ihb, icb);

    // 2. fc_w convert (fp16 single-term, 64x prescale)
    conv4_f16s<<<((size_t)Vdim*Hdim/4+255)/256, 256>>>(fc_w, fwh16, Vdim*Hdim/4);

    // 3. remaining operand prep
    gather16_kernel<<<MT, 128>>>(embedding, captions);
    split_permute2_kernel<<<2048, 256>>>(W_ih, W_hh);

    // 4. gx = (emb16 @ Wih16'^T)/64 + pbias (compact rows)
    {
        dim3 grid(G4/128, MT/128);
        gx_gemm<<<grid, 256, GX_DSM>>>(emb16, wih16h, wih16l, gx, pbias);
    }

    // 5. full recurrence in ONE persistent launch (128 blocks, 4 mtiles)
    persist_step_kernel<<<128, 256, PK_BYTES>>>();

    // 6. fc projection (fp16 single-term, 1/64 scale) + masked zeros fused
    {
        dim3 grid((Vdim + 127)/128, MT/128);
        fc_gemm<<<grid, 256, FC_DSM>>>(hall16, fwh16, out, fc_b);
    }
}

// round 17
// speedup vs baseline: 1.1537x; 1.1537x over previous
#include <cuda_runtime.h>
#include <cuda_bf16.h>
#include <cuda_fp16.h>
#include <cstdint>
#include <math.h>

#define Bdim 128
#define Tdim 32
#define Edim 512
#define Hdim 512
#define Vdim 10000
#define LFdim 49
#define G4 2048
#define MT 4096
#define Kdim 512

// ---------------- scratch (__device__ globals; no allocs allowed) ----------
__device__ float g_mf[Bdim*Edim];              // fp32 mean-pooled features
__device__ float g_c[Bdim*Hdim];
__device__ float g_gx[(size_t)MT*G4];          // compact rows (bias folded)
__device__ float g_pbias[G4];                  // permuted b_ih+b_hh

__device__ int g_nact[Tdim];
__device__ int g_off[Tdim+1];
__device__ int g_Mc;
__device__ int g_map[MT];   // row -> (t<<8)|b ; bit16 set = masked (zero output)
__device__ unsigned int g_sync2[128];          // per-mtile counters at [mtile*32]

__device__ __half g_h016[Bdim*Hdim];           // initial hidden state (fp16)
__device__ __half g_emb16[(size_t)MT*Edim];    // gathered embeddings (fp16)
__device__ __half g_wih16h[(size_t)G4*Edim], g_wih16l[(size_t)G4*Edim]; // perm, x64
__device__ __half g_whh16h[(size_t)G4*Hdim], g_whh16l[(size_t)G4*Hdim]; // perm, x64
__device__ __half g_fwh16[(size_t)Vdim*Hdim];  // 64x prescaled fp16
__device__ __half g_hall16[(size_t)MT*Hdim];   // compact hidden states, fp16

// ---------------- PTX helpers (sm_80-era: legal on base sm_100) ------------
__device__ __forceinline__ uint32_t smem_to_u32(const void* p) {
    uint32_t a;
    asm("{ .reg .u64 t; cvta.to.shared.u64 t, %1; cvt.u32.u64 %0, t; }" : "=r"(a) : "l"(p));
    return a;
}
__device__ __forceinline__ void cp16(uint32_t dst, const void* src, bool pred) {
    int sz = pred ? 16 : 0;
    asm volatile("cp.async.cg.shared.global [%0], [%1], 16, %2;"
                 :: "r"(dst), "l"(src), "r"(sz) : "memory");
}
#define CP_COMMIT() asm volatile("cp.async.commit_group;" ::: "memory")
#define CP_WAIT2()  asm volatile("cp.async.wait_group 2;" ::: "memory")
#define CP_WAIT1()  asm volatile("cp.async.wait_group 1;" ::: "memory")
#define CP_WAIT0()  asm volatile("cp.async.wait_group 0;" ::: "memory")
#define LDSM4(r, addr) \
    asm volatile("ldmatrix.sync.aligned.m8n8.x4.shared.b16 {%0,%1,%2,%3}, [%4];" \
        : "=r"((r)[0]), "=r"((r)[1]), "=r"((r)[2]), "=r"((r)[3]) : "r"(addr))

__device__ __forceinline__ void mma16816h(float* c, const uint32_t* a, const uint32_t* b) {
    asm volatile("mma.sync.aligned.m16n8k16.row.col.f32.f16.f16.f32 "
        "{%0,%1,%2,%3}, {%4,%5,%6,%7}, {%8,%9}, {%0,%1,%2,%3};"
        : "+f"(c[0]), "+f"(c[1]), "+f"(c[2]), "+f"(c[3])
        : "r"(a[0]), "r"(a[1]), "r"(a[2]), "r"(a[3]), "r"(b[0]), "r"(b[1]));
}

// XOR swizzle for 64B-row tiles: row r, 16B chunk q
__device__ __forceinline__ uint32_t sw_off(int r, int q) {
    return (uint32_t)(r*64 + ((q ^ ((r >> 1) & 3)) << 4));
}

__device__ __forceinline__ float sigf(float x) { return 1.0f / (1.0f + expf(-x)); }

__device__ __forceinline__ uint32_t pack_h2(float a, float b) {
    __half2 v = __floats2half2_rn(a, b);
    return *(uint32_t*)&v;
}

#define INV64 0.015625f

// ---------------------------------------------------------------------------
// setup: n_active(t), offsets, full row map (active + masked pads), biases
__global__ void setup_kernel(const int* __restrict__ lengths,
                             const float* __restrict__ b_ih,
                             const float* __restrict__ b_hh) {
    __shared__ int s_len[Bdim];
    __shared__ int s_moff[Bdim];     // prefix of masked counts per batch
    int tid = threadIdx.x;
    if (tid < 128) g_sync2[tid] = 0u;
    if (tid < Bdim) s_len[tid] = lengths[tid];
    __syncthreads();
    if (tid < Tdim) {
        int cnt = 0;
        for (int b = 0; b < Bdim; b++) cnt += (s_len[b] > tid) ? 1 : 0;
        g_nact[tid] = cnt;
    }
    __syncthreads();
    if (tid == 0) {
        int acc = 0;
        for (int t = 0; t < Tdim; t++) { g_off[t] = acc; acc += g_nact[t]; }
        g_off[Tdim] = acc;
        g_Mc = acc;
        int macc = 0;
        for (int b = 0; b < Bdim; b++) { s_moff[b] = macc; macc += Tdim - s_len[b]; }
    }
    __syncthreads();
    int Mc = g_Mc;
    for (int r = tid; r < Mc; r += 256) {
        int t = 0;
        while (t < Tdim - 1 && r >= g_off[t+1]) t++;
        g_map[r] = (t << 8) | (r - g_off[t]);
    }
    for (int i = tid; i < MT; i += 256) {
        int b = i >> 5, t = i & 31;
        if (t >= s_len[b]) {
            int rp = Mc + s_moff[b] + (t - s_len[b]);
            g_map[rp] = (t << 8) | b | 0x10000;
        }
    }
    for (int i = tid; i < G4; i += 256) {
        int j = i >> 2, g = i & 3;
        g_pbias[i] = b_ih[g*512 + j] + b_hh[g*512 + j];
    }
}

// ---------------------------------------------------------------------------
// mean pool -> fp32
__global__ void meanpool_kernel(const float* __restrict__ features) {
    int b = blockIdx.x, k = threadIdx.x;
    const float* p = features + (size_t)b*LFdim*512 + k;
    float s = 0.f;
    #pragma unroll
    for (int l = 0; l < LFdim; l++) s += p[l*512];
    g_mf[b*512 + k] = s * (1.0f/LFdim);
}

// exact fp32 init GEMM: h0 (-> fp16) and c0 (fp32).
__global__ void __launch_bounds__(256)
init_kernel(const float* __restrict__ ihw, const float* __restrict__ icw,
            const float* __restrict__ ihb, const float* __restrict__ icb) {
    __shared__ float ws[8*512];      // 16 KB: this block's 8 weight rows
    const int nb = blockIdx.x * 8;   // stacked unit base (0..1016)
    const int tid = threadIdx.x;
    for (int i = tid; i < 8*128; i += 256) {
        int rr = i >> 7, c4 = (i & 127) * 4;
        int n = nb + rr;
        const float* src = (n < 512) ? (ihw + (size_t)n*512 + c4)
                                     : (icw + (size_t)(n-512)*512 + c4);
        *(float4*)(ws + rr*512 + c4) = *(const float4*)src;
    }
    __syncthreads();

    const int u = tid & 7;
    const int bg = tid >> 3;
    const int n = nb + u;
    const float bias = (n < 512) ? ihb[n] : icb[n - 512];
    const float* w = ws + u*512;
    const float* m0 = g_mf + (bg*4 + 0)*512;
    const float* m1 = g_mf + (bg*4 + 1)*512;
    const float* m2 = g_mf + (bg*4 + 2)*512;
    const float* m3 = g_mf + (bg*4 + 3)*512;
    float a0 = 0.f, a1 = 0.f, a2 = 0.f, a3 = 0.f;
    #pragma unroll 8
    for (int k = 0; k < 512; k += 4) {
        float4 wv = *(const float4*)(w + k);
        float4 x0 = *(const float4*)(m0 + k);
        float4 x1 = *(const float4*)(m1 + k);
        float4 x2 = *(const float4*)(m2 + k);
        float4 x3 = *(const float4*)(m3 + k);
        a0 = fmaf(wv.x, x0.x, fmaf(wv.y, x0.y, fmaf(wv.z, x0.z, fmaf(wv.w, x0.w, a0))));
        a1 = fmaf(wv.x, x1.x, fmaf(wv.y, x1.y, fmaf(wv.z, x1.z, fmaf(wv.w, x1.w, a1))));
        a2 = fmaf(wv.x, x2.x, fmaf(wv.y, x2.y, fmaf(wv.z, x2.z, fmaf(wv.w, x2.w, a2))));
        a3 = fmaf(wv.x, x3.x, fmaf(wv.y, x3.y, fmaf(wv.z, x3.z, fmaf(wv.w, x3.w, a3))));
    }
    float acc[4] = {a0 + bias, a1 + bias, a2 + bias, a3 + bias};
    #pragma unroll
    for (int i = 0; i < 4; i++) {
        int b = bg*4 + i;
        if (n < 512) g_h016[b*512 + n] = __float2half_rn(acc[i]);
        else         g_c[b*512 + n - 512] = acc[i];
    }
}

// ---------------------------------------------------------------------------
// gather embeddings into compact rows as fp16 (zero pads emb & hall16)
__global__ void gather16_kernel(const float* __restrict__ emb,
                                const int* __restrict__ cap) {
    int r = blockIdx.x;
    int v = g_map[r];
    int c4 = threadIdx.x * 4;          // 128 threads x 4 = 512
    if (v & 0x10000) {
        uint2 z = make_uint2(0u, 0u);
        *(uint2*)(g_emb16 + (size_t)r*Edim + c4) = z;
        *(uint2*)(g_hall16 + (size_t)r*Hdim + c4) = z;
        return;
    }
    int t = (v >> 8) & 0xFF, b = v & 0xFF;
    int tok = cap[b*Tdim + t];
    float4 x = *(const float4*)(emb + (size_t)tok*Edim + c4);
    *(uint2*)(g_emb16 + (size_t)r*Edim + c4) =
        make_uint2(pack_h2(x.x, x.y), pack_h2(x.z, x.w));
}

// split BOTH recurrent weights: gate-permuted, fp16 2-term, x64 prescale
__global__ void split_permute2_kernel(const float* __restrict__ Wih,
                                      const float* __restrict__ Whh) {
    int bi = blockIdx.x;
    const float* W = (bi < 1024) ? Wih : Whh;
    __half* hi = (bi < 1024) ? g_wih16h : g_whh16h;
    __half* lo = (bi < 1024) ? g_wih16l : g_whh16l;
    int idx = (bi & 1023)*256 + threadIdx.x;
    int r = idx >> 7, c4 = (idx & 127) * 4;
    int j = r >> 2, g = r & 3;
    float4 x = *(const float4*)(W + (size_t)(g*512 + j)*512 + c4);
    x.x *= 64.f; x.y *= 64.f; x.z *= 64.f; x.w *= 64.f;
    float hx = __half2float(__float2half_rn(x.x));
    float hy = __half2float(__float2half_rn(x.y));
    float hz = __half2float(__float2half_rn(x.z));
    float hw = __half2float(__float2half_rn(x.w));
    *(uint2*)(hi + (size_t)r*512 + c4) = make_uint2(pack_h2(x.x, x.y), pack_h2(x.z, x.w));
    *(uint2*)(lo + (size_t)r*512 + c4) =
        make_uint2(pack_h2(x.x - hx, x.y - hy), pack_h2(x.z - hz, x.w - hw));
}

// vectorized fp16 convert with 64x prescale (fc_w, single-term)
__global__ void conv4_f16s(const float* __restrict__ s,
                           __half* __restrict__ hi, int n4) {
    int i = blockIdx.x*256 + threadIdx.x;
    if (i >= n4) return;
    float4 x = ((const float4*)s)[i];
    ((uint2*)hi)[i] = make_uint2(pack_h2(x.x*64.f, x.y*64.f), pack_h2(x.z*64.f, x.w*64.f));
}

// ---------------------------------------------------------------------------
// gx GEMM: fp16 A-single + W-double (x64). C = (A@(Wh+Wl)^T)/64 + pbias.
// Block 128x128, BK=32, 3-stage pipeline (24 KB/stage, 72 KB), 2 CTAs/SM.
#define GX_TILE 8192
#define GX_STAGE (3*GX_TILE)
#define GX_DSM (3*GX_STAGE)     // 72 KB

__global__ void __launch_bounds__(256, 2)
gx_gemm(const __half* __restrict__ A, const __half* __restrict__ Bh,
        const __half* __restrict__ Bl, float* __restrict__ C,
        const float* __restrict__ b1)
{
    const int m0 = blockIdx.y * 128;
    if (m0 >= g_Mc) return;
    extern __shared__ char smem[];
    const uint32_t sbase = smem_to_u32(smem);
    const int tid = threadIdx.x;
    const int lane = tid & 31, wid = tid >> 5;
    const int wm = wid >> 2, wn = wid & 3;
    const int n0 = blockIdx.x * 128;
    const int N = G4;

    float c[4][4][4];
    #pragma unroll
    for (int i = 0; i < 4; i++)
        #pragma unroll
        for (int j = 0; j < 4; j++)
            { c[i][j][0]=0.f; c[i][j][1]=0.f; c[i][j][2]=0.f; c[i][j][3]=0.f; }

    auto load_stage = [&](int kc, int stage) {
        const int k0 = kc * 32;
        const uint32_t st = sbase + stage * GX_STAGE;
        #pragma unroll
        for (int i = 0; i < 2; i++) {
            int chunk = tid + 256*i;
            int r = chunk >> 2, q = chunk & 3;
            uint32_t off = sw_off(r, q);
            cp16(st + off, A + (size_t)(m0 + r)*Kdim + k0 + q*8, true);
            size_t bo = (size_t)(n0 + r)*Kdim + k0 + q*8;
            cp16(st + GX_TILE + off,   Bh + bo, true);
            cp16(st + 2*GX_TILE + off, Bl + bo, true);
        }
        CP_COMMIT();
    };

    const int NK = Kdim / 32;   // 16
    load_stage(0, 0);
    load_stage(1, 1);
    for (int kc = 0; kc < NK; kc++) {
        int stage = kc % 3;
        if (kc + 2 < NK)      CP_WAIT2();
        else if (kc + 1 < NK) CP_WAIT1();
        else                  CP_WAIT0();
        __syncthreads();
        if (kc + 2 < NK) load_stage(kc + 2, (kc + 2) % 3);
        const uint32_t sa = sbase + stage * GX_STAGE;

        #pragma unroll
        for (int kh = 0; kh < 2; kh++) {
            uint32_t aH[4][4];
            #pragma unroll
            for (int mf = 0; mf < 4; mf++) {
                int row  = wm*64 + mf*16 + (lane & 7) + ((lane >> 3) & 1)*8;
                int kcol = kh*16 + ((lane >> 4) & 1)*8;
                LDSM4(aH[mf], sa + sw_off(row, kcol >> 3));
            }
            uint32_t bH[4][2], bL[4][2];
            #pragma unroll
            for (int np = 0; np < 2; np++) {
                int row  = wn*32 + np*16 + (lane & 7) + ((lane >> 4) & 1)*8;
                int kcol = ((lane >> 3) & 1)*8 + kh*16;
                uint32_t off = sw_off(row, kcol >> 3);
                uint32_t r4[4];
                LDSM4(r4, sa + GX_TILE + off);
                bH[np*2][0]=r4[0]; bH[np*2][1]=r4[1];
                bH[np*2+1][0]=r4[2]; bH[np*2+1][1]=r4[3];
                LDSM4(r4, sa + 2*GX_TILE + off);
                bL[np*2][0]=r4[0]; bL[np*2][1]=r4[1];
                bL[np*2+1][0]=r4[2]; bL[np*2+1][1]=r4[3];
            }
            #pragma unroll
            for (int mf = 0; mf < 4; mf++)
                #pragma unroll
                for (int nf = 0; nf < 4; nf++) {
                    mma16816h(c[mf][nf], aH[mf], bH[nf]);
                    mma16816h(c[mf][nf], aH[mf], bL[nf]);
                }
        }
    }

    #pragma unroll
    for (int mf = 0; mf < 4; mf++) {
        #pragma unroll
        for (int nf = 0; nf < 4; nf++) {
            int m = m0 + wm*64 + mf*16 + (lane >> 2);
            int n = n0 + wn*32 + nf*8 + 2*(lane & 3);
            #pragma unroll
            for (int half = 0; half < 2; half++) {
                int mm = m + half*8;
                float v0 = c[mf][nf][half*2]*INV64   + b1[n];
                float v1 = c[mf][nf][half*2+1]*INV64 + b1[n+1];
                *(float2*)(C + (size_t)mm*N + n) = make_float2(v0, v1);
            }
        }
    }
}

// ---------------------------------------------------------------------------
// fc GEMM: fp16 single-term, BK=32, 4-stage pipeline (16 KB/stage, 64 KB).
#define FC_TILE 8192
#define FC_STAGE (2*FC_TILE)
#define FC_DSM (4*FC_STAGE)     // 64 KB

__global__ void __launch_bounds__(256, 2)
fc_gemm(const __half* __restrict__ A, const __half* __restrict__ Bh,
        float* __restrict__ C, const float* __restrict__ b1)
{
    const int m0 = blockIdx.y * 128;
    extern __shared__ char smem[];
    const uint32_t sbase = smem_to_u32(smem);
    const int tid = threadIdx.x;
    const int lane = tid & 31, wid = tid >> 5;
    const int wm = wid >> 2, wn = wid & 3;
    const int n0 = blockIdx.x * 128;
    const int N = Vdim;

    float c[4][4][4];
    #pragma unroll
    for (int i = 0; i < 4; i++)
        #pragma unroll
        for (int j = 0; j < 4; j++)
            { c[i][j][0]=0.f; c[i][j][1]=0.f; c[i][j][2]=0.f; c[i][j][3]=0.f; }

    if (m0 < g_Mc) {
        auto load_stage = [&](int kc, int stage) {
            const int k0 = kc * 32;
            const uint32_t st = sbase + stage * FC_STAGE;
            #pragma unroll
            for (int i = 0; i < 2; i++) {
                int chunk = tid + 256*i;
                int r = chunk >> 2, q = chunk & 3;
                uint32_t off = sw_off(r, q);
                cp16(st + off, A + (size_t)(m0 + r)*Kdim + k0 + q*8, true);
                int nr = n0 + r;
                bool bp = nr < N;
                size_t bo = (size_t)(bp ? nr : (N-1))*Kdim + k0 + q*8;
                cp16(st + FC_TILE + off, Bh + bo, bp);
            }
            CP_COMMIT();
        };

        const int NK = Kdim / 32;   // 16
        load_stage(0, 0);
        load_stage(1, 1);
        load_stage(2, 2);
        for (int kc = 0; kc < NK; kc++) {
            int stage = kc & 3;
            if (kc + 2 < NK)      CP_WAIT2();
            else if (kc + 1 < NK) CP_WAIT1();
            else                  CP_WAIT0();
            __syncthreads();
            if (kc + 3 < NK) load_stage(kc + 3, (kc + 3) & 3);
            const uint32_t sa = sbase + stage * FC_STAGE;

            #pragma unroll
            for (int kh = 0; kh < 2; kh++) {
                uint32_t aH[4][4];
                #pragma unroll
                for (int mf = 0; mf < 4; mf++) {
                    int row  = wm*64 + mf*16 + (lane & 7) + ((lane >> 3) & 1)*8;
                    int kcol = kh*16 + ((lane >> 4) & 1)*8;
                    LDSM4(aH[mf], sa + sw_off(row, kcol >> 3));
                }
                uint32_t bHf[4][2];
                #pragma unroll
                for (int np = 0; np < 2; np++) {
                    int row  = wn*32 + np*16 + (lane & 7) + ((lane >> 4) & 1)*8;
                    int kcol = ((lane >> 3) & 1)*8 + kh*16;
                    uint32_t r4[4];
                    LDSM4(r4, sa + FC_TILE + sw_off(row, kcol >> 3));
                    bHf[np*2][0]=r4[0]; bHf[np*2][1]=r4[1];
                    bHf[np*2+1][0]=r4[2]; bHf[np*2+1][1]=r4[3];
                }
                #pragma unroll
                for (int mf = 0; mf < 4; mf++)
                    #pragma unroll
                    for (int nf = 0; nf < 4; nf++)
                        mma16816h(c[mf][nf], aH[mf], bHf[nf]);
            }
        }
    }

    #pragma unroll
    for (int mf = 0; mf < 4; mf++) {
        #pragma unroll
        for (int nf = 0; nf < 4; nf++) {
            int m = m0 + wm*64 + mf*16 + (lane >> 2);
            int n = n0 + wn*32 + nf*8 + 2*(lane & 3);
            if (n >= N) continue;
            #pragma unroll
            for (int half = 0; half < 2; half++) {
                int mm = m + half*8;
                int v = g_map[mm];
                int t = (v >> 8) & 0xFF, b = v & 0xFF;
                float2 o;
                if (v & 0x10000) {
                    o = make_float2(0.f, 0.f);
                } else {
                    o = make_float2(c[mf][nf][half*2]*INV64   + b1[n],
                                    c[mf][nf][half*2+1]*INV64 + b1[n+1]);
                }
                *(float2*)(C + ((size_t)(b*Tdim + t))*Vdim + n) = o;
            }
        }
    }
}

// ---------------------------------------------------------------------------
// Persistent recurrence, fp16. W resident; FULL A tile (32x512, 32KB) loaded
// once per step -> ZERO barriers inside the 16-kc MMA loop. (R15, unchanged)
#define PK_WH    0
#define PK_WL    65536
#define PK_A     131072          // 16 chunks x 2 KB = 32 KB
#define PK_GATES 163840          // float[32*66] = 8448 B
#define PK_CST   172288          // float[512]   = 2048 B
#define PK_BYTES 174336

__global__ void __launch_bounds__(256)
persist_step_kernel() {
    extern __shared__ char sm[];
    const uint32_t sbase = smem_to_u32(sm);
    const int tid = threadIdx.x;
    const int lane = tid & 31, wid = tid >> 5;
    const int wm = wid >> 2, wn = wid & 3;   // 2m x 4n warp grid (32 x 64 tile)
    const int nslice = blockIdx.x & 31;
    const int mtile = blockIdx.x >> 5;       // 0..3
    const int n0 = nslice * 64;
    const int m0 = mtile * 32;
    unsigned int* syncc = &g_sync2[mtile * 32];

    {
        int r = tid >> 2, q = tid & 3;
        #pragma unroll
        for (int kc = 0; kc < 16; kc++) {
            uint32_t off = (uint32_t)(kc*4096) + sw_off(r, q);
            size_t go = (size_t)(n0 + r)*Hdim + kc*32 + q*8;
            cp16(sbase + PK_WH + off, g_whh16h + go, true);
            cp16(sbase + PK_WL + off, g_whh16l + go, true);
        }
        CP_COMMIT();
    }
    float* cst = (float*)(sm + PK_CST);      // [32 rows x 16 units]
    for (int i = tid; i < 512; i += 256) {
        int r = i >> 4, u = i & 15;
        cst[i] = g_c[(m0 + r)*Hdim + (n0 >> 2) + u];
    }
    CP_WAIT0();
    __syncthreads();

    float* gs = (float*)(sm + PK_GATES);
    int scount = 0;

    for (int t = 0; t < Tdim; t++) {
        const int nact = g_nact[t];
        if (mtile > 0 && nact <= m0) break;  // nact non-increasing: done forever
        const __half* Ah = (t == 0) ? g_h016 : (g_hall16 + (size_t)g_off[t-1]*Hdim);

        {
            for (int i = tid; i < 2048; i += 256) {
                int kc = i >> 7, rem = i & 127;
                int r = rem >> 2, q = rem & 3;
                cp16(sbase + PK_A + (uint32_t)(kc*2048) + sw_off(r, q),
                     Ah + (size_t)(m0 + r)*Hdim + kc*32 + q*8, true);
            }
            CP_COMMIT();
            CP_WAIT0();
            __syncthreads();

            float acc[2][4];
            #pragma unroll
            for (int j = 0; j < 2; j++)
                { acc[j][0]=0.f; acc[j][1]=0.f; acc[j][2]=0.f; acc[j][3]=0.f; }

            #pragma unroll 4
            for (int kc = 0; kc < 16; kc++) {
                const uint32_t sa  = sbase + PK_A  + (uint32_t)(kc*2048);
                const uint32_t wbH = sbase + PK_WH + (uint32_t)(kc*4096);
                const uint32_t wbL = sbase + PK_WL + (uint32_t)(kc*4096);
                #pragma unroll
                for (int kh = 0; kh < 2; kh++) {
                    uint32_t aH[4];
                    {
                        int row  = wm*16 + (lane & 7) + ((lane >> 3) & 1)*8;
                        int kcol = kh*16 + ((lane >> 4) & 1)*8;
                        LDSM4(aH, sa + sw_off(row, kcol >> 3));
                    }
                    uint32_t bH[2][2], bL[2][2];
                    {
                        int row  = wn*16 + (lane & 7) + ((lane >> 4) & 1)*8;
                        int kcol = ((lane >> 3) & 1)*8 + kh*16;
                        uint32_t off = sw_off(row, kcol >> 3);
                        uint32_t r4[4];
                        LDSM4(r4, wbH + off);
                        bH[0][0]=r4[0]; bH[0][1]=r4[1]; bH[1][0]=r4[2]; bH[1][1]=r4[3];
                        LDSM4(r4, wbL + off);
                        bL[0][0]=r4[0]; bL[0][1]=r4[1]; bL[1][0]=r4[2]; bL[1][1]=r4[3];
                    }
                    #pragma unroll
                    for (int nf = 0; nf < 2; nf++) {
                        mma16816h(acc[nf], aH, bH[nf]);
                        mma16816h(acc[nf], aH, bL[nf]);
                    }
                }
            }

            const int goff = g_off[t];
            #pragma unroll
            for (int nf = 0; nf < 2; nf++) {
                int rl = wm*16 + (lane >> 2);
                int nl = wn*16 + nf*8 + 2*(lane & 3);
                #pragma unroll
                for (int half = 0; half < 2; half++) {
                    int rr = rl + half*8;
                    float2 gx2 = *(const float2*)(g_gx + (size_t)(goff + m0 + rr)*G4 + n0 + nl);
                    gs[rr*66 + nl]     = acc[nf][half*2]*INV64   + gx2.x;
                    gs[rr*66 + nl + 1] = acc[nf][half*2+1]*INV64 + gx2.y;
                }
            }
            __syncthreads();

            #pragma unroll
            for (int p = 0; p < 2; p++) {
                int idx = tid + 256*p;
                int row = idx >> 4, u = idx & 15;
                int rg = m0 + row;
                if (rg < nact) {
                    float gi = gs[row*66 + u*4 + 0];
                    float gf = gs[row*66 + u*4 + 1];
                    float gc = gs[row*66 + u*4 + 2];
                    float go = gs[row*66 + u*4 + 3];
                    float cc = cst[row*16 + u];
                    cc = sigf(gf)*cc + sigf(gi)*tanhf(gc);
                    float hv = sigf(go)*tanhf(cc);
                    cst[row*16 + u] = cc;
                    int jg = (n0 >> 2) + u;
                    g_hall16[(size_t)(goff + rg)*Hdim + jg] = __float2half_rn(hv);
                }
            }
        }

        scount++;
        __syncthreads();
        if (tid == 0) {
            __threadfence();
            atomicAdd(syncc, 1u);
            unsigned target = 32u * (unsigned)scount;
            while (atomicAdd(syncc, 0u) < target) { __nanosleep(32); }
            __threadfence();
        }
        __syncthreads();
    }
}

// ---------------------------------------------------------------------------
extern "C" void kernel_launch(void* const* d_in, const int* in_sizes, int n_in,
                              void* d_out, int out_size) {
    const float* features  = (const float*)d_in[0];
    const int*   captions  = (const int*)  d_in[1];
    const int*   lengths   = (const int*)  d_in[2];
    const float* embedding = (const float*)d_in[3];
    const float* W_ih      = (const float*)d_in[4];
    const float* W_hh      = (const float*)d_in[5];
    const float* b_ih      = (const float*)d_in[6];
    const float* b_hh      = (const float*)d_in[7];
    const float* fc_w      = (const float*)d_in[8];
    const float* fc_b      = (const float*)d_in[9];
    const float* ihw       = (const float*)d_in[10];
    const float* ihb       = (const float*)d_in[11];
    const float* icw       = (const float*)d_in[12];
    const float* icb       = (const float*)d_in[13];
    float* out = (float*)d_out;

    float *gx, *pbias;
    __half *emb16, *wih16h, *wih16l, *fwh16, *hall16;
    cudaGetSymbolAddress((void**)&gx, g_gx);
    cudaGetSymbolAddress((void**)&pbias, g_pbias);
    cudaGetSymbolAddress((void**)&emb16, g_emb16);
    cudaGetSymbolAddress((void**)&wih16h, g_wih16h);
    cudaGetSymbolAddress((void**)&wih16l, g_wih16l);
    cudaGetSymbolAddress((void**)&fwh16, g_fwh16);
    cudaGetSymbolAddress((void**)&hall16, g_hall16);

    cudaFuncSetAttribute(gx_gemm, cudaFuncAttributeMaxDynamicSharedMemorySize, GX_DSM);
    cudaFuncSetAttribute(fc_gemm, cudaFuncAttributeMaxDynamicSharedMemorySize, FC_DSM);
    cudaFuncSetAttribute(persist_step_kernel, cudaFuncAttributeMaxDynamicSharedMemorySize, PK_BYTES);

    // 0. row map + biases + sync reset
    setup_kernel<<<1, 256>>>(lengths, b_ih, b_hh);

    // 1. mean pool + exact fp32 init (h0 -> fp16, c0 fp32)
    meanpool_kernel<<<Bdim, 512>>>(features);
    init_kernel<<<128, 256>>>(ihw, icw, ihb, icb);

    // 2. fc_w convert (fp16 single-term, 64x prescale)
    conv4_f16s<<<((size_t)Vdim*Hdim/4+255)/256, 256>>>(fc_w, fwh16, Vdim*Hdim/4);

    // 3. remaining operand prep
    gather16_kernel<<<MT, 128>>>(embedding, captions);
    split_permute2_kernel<<<2048, 256>>>(W_ih, W_hh);

    // 4. gx = (emb16 @ Wih16'^T)/64 + pbias (compact rows)
    {
        dim3 grid(G4/128, MT/128);
        gx_gemm<<<grid, 256, GX_DSM>>>(emb16, wih16h, wih16l, gx, pbias);
    }

    // 5. full recurrence in ONE persistent launch (128 blocks, 4 mtiles)
    persist_step_kernel<<<128, 256, PK_BYTES>>>();

    // 6. fc projection (fp16 single-term, 1/64 scale) + masked zeros fused
    {
        dim3 grid((Vdim + 127)/128, MT/128);
        fc_gemm<<<grid, 256, FC_DSM>>>(hall16, fwh16, out, fc_b);
    }
}